// round 14
// baseline (speedup 1.0000x reference)
#include <cuda_runtime.h>
#include <cuda_fp16.h>

#define N_NODES_C 50000
#define N_EDGES_C 800000
#define HID_C 64
#define N_GRAPHS_C 256
#define BN_EPS_C 1e-5f
#define GATE_EPS_C 1e-6f
#define SCAN_TILE 1024
#define N_TILES ((N_NODES_C + SCAN_TILE - 1) / SCAN_TILE)

// ---------------- persistent device scratch ----------------
// ping-pong node state: per (node, lane) float4 = (hf_l[2l], hf_l[2l+1], hpre_l[2l], hpre_l[2l+1])
__device__ float4 g_hf2[2][(size_t)N_NODES_C * 32];
__device__ __half2 g_efh[(size_t)N_EDGES_C * 32];  // edge features fp16 (dst-sorted)
__device__ float g_norm[N_NODES_C];
__device__ int   g_deg[N_NODES_C];
__device__ int   g_cursor[N_NODES_C];
__device__ int   g_rowptr[N_NODES_C + 1];
__device__ int   g_srcs[N_EDGES_C];                // packed: src(16) | etype(2)<<16 | hidx(7)<<18
__device__ int   g_bsum[N_TILES];
__device__ int   g_boff[N_TILES];
__device__ float g_stats4[4][256];                 // per-layer [se, se2, sh, sh2]
__device__ float g_hg[N_GRAPHS_C * HID_C];
__device__ int   g_gcount[N_GRAPHS_C];

// ---- streaming (evict-first) access helpers for the big ef array ----
__device__ __forceinline__ unsigned long long mk_policy() {
    unsigned long long p;
    asm volatile("createpolicy.fractional.L2::evict_first.b64 %0, 1.0;" : "=l"(p));
    return p;
}
__device__ __forceinline__ unsigned ld_stream_b32(const void* ptr, unsigned long long pol) {
    unsigned v;
    asm volatile("ld.global.L2::cache_hint.b32 %0, [%1], %2;"
                 : "=r"(v) : "l"(ptr), "l"(pol));
    return v;
}
__device__ __forceinline__ void st_stream_b32(void* ptr, unsigned v, unsigned long long pol) {
    asm volatile("st.global.L2::cache_hint.b32 [%0], %1, %2;"
                 :: "l"(ptr), "r"(v), "l"(pol));
}

// sigmoid via single-MUFU hardware tanh: sigma(x) = 0.5*tanh(x/2) + 0.5
__device__ __forceinline__ float fast_sigmoid(float x) {
    float t;
    asm("tanh.approx.f32 %0, %1;" : "=f"(t) : "f"(x * 0.5f));
    return fmaf(t, 0.5f, 0.5f);
}

// BN scale/shift for one feature from raw sums
__device__ __forceinline__ void bn_coeff(float s, float s2, float invN,
                                         float gamma, float beta,
                                         float& scale, float& shift) {
    float mu = s * invN;
    float var = s2 * invN - mu * mu;
    scale = gamma * rsqrtf(var + BN_EPS_C);
    shift = beta - mu * scale;
}

// ---------------- prep kernels (R12-proven structure) ----------------

__global__ void k_init() {
    int i = blockIdx.x * blockDim.x + threadIdx.x;
    if (i < N_NODES_C) { g_deg[i] = 0; g_cursor[i] = 0; }
    if (i < N_GRAPHS_C * HID_C) g_hg[i] = 0.f;
    if (i < N_GRAPHS_C) g_gcount[i] = 0;
    if (i < 4 * 256) ((float*)g_stats4)[i] = 0.f;
}

__global__ void k_deg(const int* __restrict__ dst, const int* __restrict__ graph_ids) {
    int i = blockIdx.x * blockDim.x + threadIdx.x;
    if (i < N_EDGES_C) atomicAdd(&g_deg[dst[i]], 1);
    if (i < N_NODES_C) atomicAdd(&g_gcount[graph_ids[i]], 1);
}

__global__ void k_nodeinit(const int* __restrict__ h, const float* __restrict__ node_emb) {
    int tid = threadIdx.x;
    int warp = tid >> 5, lane = tid & 31;
    int n = blockIdx.x * 8 + warp;
    if (n >= N_NODES_C) return;
    if (lane == 0) g_norm[n] = rsqrtf(fmaxf((float)g_deg[n], 1.f));
    int hi = h[n];
    float2 v = *(const float2*)(node_emb + hi * HID_C + 2 * lane);
    g_hf2[0][(size_t)n * 32 + lane] = make_float4(v.x, v.y, 0.f, 0.f);
}

__global__ void k_scanA() {
    __shared__ int s[32];
    int b = blockIdx.x, tid = threadIdx.x;
    int i = b * SCAN_TILE + tid;
    int v = (i < N_NODES_C) ? g_deg[i] : 0;
    #pragma unroll
    for (int off = 16; off > 0; off >>= 1) v += __shfl_down_sync(0xFFFFFFFFu, v, off);
    if ((tid & 31) == 0) s[tid >> 5] = v;
    __syncthreads();
    if (tid < 32) {
        int w = s[tid];
        #pragma unroll
        for (int off = 16; off > 0; off >>= 1) w += __shfl_down_sync(0xFFFFFFFFu, w, off);
        if (tid == 0) g_bsum[b] = w;
    }
}

__global__ void k_scanB() {
    int tid = threadIdx.x;
    int v = (tid < N_TILES) ? g_bsum[tid] : 0;
    int x = v;
    #pragma unroll
    for (int off = 1; off < 64; off <<= 1) {
        int t = __shfl_up_sync(0xFFFFFFFFu, x, off);
        if ((tid & 31) >= off) x += t;
    }
    __shared__ int s_half;
    if (tid == 31) s_half = x;
    __syncthreads();
    if (tid >= 32) x += s_half;
    if (tid < N_TILES) g_boff[tid] = x - v;
}

__global__ void k_scanC() {
    __shared__ int s_warp[32];
    int b = blockIdx.x, tid = threadIdx.x;
    int lane = tid & 31, warp = tid >> 5;
    int i = b * SCAN_TILE + tid;
    int v = (i < N_NODES_C) ? g_deg[i] : 0;
    int x = v;
    #pragma unroll
    for (int off = 1; off < 32; off <<= 1) {
        int t = __shfl_up_sync(0xFFFFFFFFu, x, off);
        if (lane >= off) x += t;
    }
    if (lane == 31) s_warp[warp] = x;
    __syncthreads();
    if (warp == 0) {
        int w = s_warp[lane];
        #pragma unroll
        for (int off = 1; off < 32; off <<= 1) {
            int t = __shfl_up_sync(0xFFFFFFFFu, w, off);
            if (lane >= off) w += t;
        }
        s_warp[lane] = w;
    }
    __syncthreads();
    int incl = x + (warp > 0 ? s_warp[warp - 1] : 0) + g_boff[b];
    if (i < N_NODES_C) g_rowptr[i + 1] = incl;
    if (b == 0 && tid == 0) g_rowptr[0] = 0;
}

// counting-sort permute; packs src | etype<<16 | h[src]<<18
__global__ void k_permute(const int* __restrict__ e, const int* __restrict__ src,
                          const int* __restrict__ dst, const int* __restrict__ h) {
    int i = blockIdx.x * blockDim.x + threadIdx.x;
    if (i >= N_EDGES_C) return;
    int d = dst[i];
    int s = src[i];
    int pos = g_rowptr[d] + atomicAdd(&g_cursor[d], 1);
    g_srcs[pos] = s | (e[i] << 16) | (h[s] << 18);
}

// ---------------- fused layer pass ----------------
// Invariant: g_hf2[L&1] holds (hf_{L-1}, hpre_{L-1}); hf_L is computed on the fly as
// hf_{L-1} + relu(BN_{L-1}^h(hpre_{L-1})). Epilogue writes (hf_L, hpre_L) to g_hf2[(L+1)&1].
// No separate k_Bh pass. 1 warp/node, 4-wide shallow pipeline (R9/R12-proven loop shape).
template<int L>
__global__ void __launch_bounds__(256) k_fused(const float* __restrict__ edge_emb,
                                               const float* __restrict__ node_emb,
                                               const float* __restrict__ beg_,
                                               const float* __restrict__ beb,
                                               const float* __restrict__ bhg,
                                               const float* __restrict__ bhb) {
    __shared__ float s_emb[4 * HID_C];
    __shared__ float s_acc[256];
    int tid = threadIdx.x;
    if (L <= 1) s_emb[tid] = edge_emb[tid];
    s_acc[tid] = 0.f;
    __syncthreads();
    int warp = tid >> 5, lane = tid & 31;
    int n = blockIdx.x * 8 + warp;
    if (n < N_NODES_C) {
        const float4* __restrict__ rd = g_hf2[L & 1];
        float4* __restrict__ wr = g_hf2[(L + 1) & 1];
        unsigned long long pol = mk_policy();

        // BN coefficients of layer L-1 (edge + node), per-thread from g_stats4[L-1]
        float sce_x = 0.f, sce_y = 0.f, she_x = 0.f, she_y = 0.f;
        float sch_x = 0.f, sch_y = 0.f, shh_x = 0.f, shh_y = 0.f;
        if (L >= 1) {
            const float* st = g_stats4[L - 1];
            const float invE = 1.f / (float)N_EDGES_C;
            const float invN = 1.f / (float)N_NODES_C;
            int f0 = 2 * lane, f1 = 2 * lane + 1;
            bn_coeff(st[f0], st[64 + f0], invE,
                     __ldg(beg_ + (L - 1) * HID_C + f0), __ldg(beb + (L - 1) * HID_C + f0),
                     sce_x, she_x);
            bn_coeff(st[f1], st[64 + f1], invE,
                     __ldg(beg_ + (L - 1) * HID_C + f1), __ldg(beb + (L - 1) * HID_C + f1),
                     sce_y, she_y);
            bn_coeff(st[128 + f0], st[192 + f0], invN,
                     __ldg(bhg + (L - 1) * HID_C + f0), __ldg(bhb + (L - 1) * HID_C + f0),
                     sch_x, shh_x);
            bn_coeff(st[128 + f1], st[192 + f1], invN,
                     __ldg(bhg + (L - 1) * HID_C + f1), __ldg(bhb + (L - 1) * HID_C + f1),
                     sch_y, shh_y);
        }

        // own node: derive current features
        float4 o = rd[(size_t)n * 32 + lane];
        float hdpx = o.x, hdpy = o.y;           // hf_{L-1}
        float hdcx, hdcy;                       // hf_L
        if (L == 0) { hdcx = o.x; hdcy = o.y; }
        else {
            hdcx = o.x + fmaxf(o.z * sch_x + shh_x, 0.f);
            hdcy = o.y + fmaxf(o.w * sch_y + shh_y, 0.f);
        }
        float nn = g_norm[n];
        float mx = 0.f, my = 0.f, dx = 0.f, dy = 0.f;
        float sex = 0.f, sey = 0.f, se2x = 0.f, se2y = 0.f;
        int beg = g_rowptr[n], end = g_rowptr[n + 1];
        int nb = (end - beg) >> 2;              // full 4-edge batches

        // fetch neighbor (cur, prev) for one edge
        auto fetch_nf = [&](int sp, float2& nc, float2& np) {
            int s = sp & 0xFFFF;
            if (L == 0) {
                int hidx = (sp >> 18) & 0x7F;
                nc = __ldg((const float2*)(node_emb + hidx * HID_C + 2 * lane));
                np = make_float2(0.f, 0.f);
            } else if (L == 1) {
                int hidx = (sp >> 18) & 0x7F;
                np = __ldg((const float2*)(node_emb + hidx * HID_C + 2 * lane)); // hf_0
                float2 hp = *((const float2*)&rd[(size_t)s * 32 + lane] + 1);    // hpre_0 (8B)
                nc.x = np.x + fmaxf(hp.x * sch_x + shh_x, 0.f);
                nc.y = np.y + fmaxf(hp.y * sch_y + shh_y, 0.f);
            } else {
                float4 v = rd[(size_t)s * 32 + lane];
                np = make_float2(v.x, v.y);
                nc.x = v.x + fmaxf(v.z * sch_x + shh_x, 0.f);
                nc.y = v.y + fmaxf(v.w * sch_y + shh_y, 0.f);
            }
        };

        auto compute = [&](int k, float2 nc, float2 np, float ns, float rawx, float rawy) {
            float efx, efy;
            if (L == 0) {
                efx = rawx; efy = rawy;
            } else {
                float epx = np.x + hdpx + rawx;
                float epy = np.y + hdpy + rawy;
                efx = rawx + fmaxf(epx * sce_x + she_x, 0.f);
                efy = rawy + fmaxf(epy * sce_y + she_y, 0.f);
                if (L < 3) {
                    __half2 hv = __floats2half2_rn(efx, efy);
                    st_stream_b32(&g_efh[(size_t)k * 32 + lane], *(unsigned*)&hv, pol);
                }
            }
            float ex = nc.x + hdcx + efx;
            float ey = nc.y + hdcy + efy;
            float sgx = fast_sigmoid(ex);
            float sgy = fast_sigmoid(ey);
            mx += sgx * nc.x * ns; my += sgy * nc.y * ns;
            dx += sgx; dy += sgy;
            if (L < 3) { sex += ex; sey += ey; se2x += ex * ex; se2y += ey * ey; }
        };

        // ---- shallow software pipeline on the sequential streams ----
        int spA[4], spB[4];
        unsigned efA[4], efB[4];
        if (nb > 0) {
            #pragma unroll
            for (int j = 0; j < 4; j++) spA[j] = g_srcs[beg + j];
            if (L >= 2) {
                #pragma unroll
                for (int j = 0; j < 4; j++)
                    efA[j] = ld_stream_b32(&g_efh[(size_t)(beg + j) * 32 + lane], pol);
            }
        }
        for (int b = 0; b < nb; b++) {
            int kk = beg + b * 4;
            if (b + 1 < nb) {
                #pragma unroll
                for (int j = 0; j < 4; j++) spB[j] = g_srcs[kk + 4 + j];
                if (L >= 2) {
                    #pragma unroll
                    for (int j = 0; j < 4; j++)
                        efB[j] = ld_stream_b32(&g_efh[(size_t)(kk + 4 + j) * 32 + lane], pol);
                }
            }
            float2 nc[4], np[4];
            #pragma unroll
            for (int j = 0; j < 4; j++) fetch_nf(spA[j], nc[j], np[j]);
            float ns[4];
            #pragma unroll
            for (int j = 0; j < 4; j++) ns[j] = g_norm[spA[j] & 0xFFFF];
            float rawx[4], rawy[4];
            #pragma unroll
            for (int j = 0; j < 4; j++) {
                if (L <= 1) {
                    int et = (spA[j] >> 16) & 3;
                    rawx[j] = s_emb[et * HID_C + 2 * lane];
                    rawy[j] = s_emb[et * HID_C + 2 * lane + 1];
                } else {
                    float2 r = __half22float2(*(__half2*)&efA[j]);
                    rawx[j] = r.x; rawy[j] = r.y;
                }
            }
            #pragma unroll
            for (int j = 0; j < 4; j++) compute(kk + j, nc[j], np[j], ns[j], rawx[j], rawy[j]);
            #pragma unroll
            for (int j = 0; j < 4; j++) { spA[j] = spB[j]; efA[j] = efB[j]; }
        }
        // tail
        for (int k = beg + nb * 4; k < end; k++) {
            int sp = g_srcs[k];
            float2 nc, np;
            fetch_nf(sp, nc, np);
            float ns = g_norm[sp & 0xFFFF];
            float rawx, rawy;
            if (L <= 1) {
                int et = (sp >> 16) & 3;
                rawx = s_emb[et * HID_C + 2 * lane];
                rawy = s_emb[et * HID_C + 2 * lane + 1];
            } else {
                unsigned u = ld_stream_b32(&g_efh[(size_t)k * 32 + lane], pol);
                float2 r = __half22float2(*(__half2*)&u);
                rawx = r.x; rawy = r.y;
            }
            compute(k, nc, np, ns, rawx, rawy);
        }

        float hpx = (hdcx * nn + mx / (dx + GATE_EPS_C)) * nn;
        float hpy = (hdcy * nn + my / (dy + GATE_EPS_C)) * nn;
        // epilogue: (hf_L, hpre_L) for the next layer / pool
        wr[(size_t)n * 32 + lane] = make_float4(hdcx, hdcy, hpx, hpy);
        if (L < 3) {
            atomicAdd(&s_acc[2 * lane], sex);
            atomicAdd(&s_acc[2 * lane + 1], sey);
            atomicAdd(&s_acc[64 + 2 * lane], se2x);
            atomicAdd(&s_acc[64 + 2 * lane + 1], se2y);
        }
        atomicAdd(&s_acc[128 + 2 * lane], hpx);
        atomicAdd(&s_acc[128 + 2 * lane + 1], hpy);
        atomicAdd(&s_acc[192 + 2 * lane], hpx * hpx);
        atomicAdd(&s_acc[192 + 2 * lane + 1], hpy * hpy);
    }
    __syncthreads();
    atomicAdd(&g_stats4[L][tid], s_acc[tid]);
}

// pooling: hf_4 = hf_3 + relu(BN_3(hpre_3)) from g_hf2[0], per-graph sum
__global__ void k_BhPool(const int* __restrict__ graph_ids,
                         const float* __restrict__ bhg, const float* __restrict__ bhb) {
    int i = blockIdx.x * blockDim.x + threadIdx.x;
    if (i >= N_NODES_C * 32) return;
    int lane = i & 31;
    int n = i >> 5;
    const float* st = g_stats4[3];
    const float invN = 1.f / (float)N_NODES_C;
    int f0 = 2 * lane, f1 = 2 * lane + 1;
    float scx, shx, scy, shy;
    bn_coeff(st[128 + f0], st[192 + f0], invN,
             __ldg(bhg + 3 * HID_C + f0), __ldg(bhb + 3 * HID_C + f0), scx, shx);
    bn_coeff(st[128 + f1], st[192 + f1], invN,
             __ldg(bhg + 3 * HID_C + f1), __ldg(bhb + 3 * HID_C + f1), scy, shy);
    float4 v = g_hf2[0][i];
    float vx = v.x + fmaxf(v.z * scx + shx, 0.f);
    float vy = v.y + fmaxf(v.w * scy + shy, 0.f);
    int g = graph_ids[n];
    atomicAdd(&g_hg[(g << 6) + f0], vx);
    atomicAdd(&g_hg[(g << 6) + f1], vy);
}

// final 3-layer MLP, one thread per graph
__global__ void k_mlp(const float* __restrict__ W1, const float* __restrict__ b1,
                      const float* __restrict__ W2, const float* __restrict__ b2,
                      const float* __restrict__ W3, const float* __restrict__ b3,
                      float* __restrict__ out) {
    __shared__ float sW1[64 * 32], sW2[32 * 16], sb1[32], sb2[16], sW3[16], sb3;
    int tid = threadIdx.x;
    for (int i = tid; i < 64 * 32; i += 256) sW1[i] = W1[i];
    for (int i = tid; i < 32 * 16; i += 256) sW2[i] = W2[i];
    if (tid < 32) sb1[tid] = b1[tid];
    if (tid < 16) { sb2[tid] = b2[tid]; sW3[tid] = W3[tid]; }
    if (tid == 0) sb3 = b3[0];
    __syncthreads();
    int g = tid;
    float inv = 1.f / fmaxf((float)g_gcount[g], 1.f);
    float x[64];
    #pragma unroll
    for (int k = 0; k < 64; k++) x[k] = g_hg[g * 64 + k] * inv;
    float y[32];
    #pragma unroll
    for (int j = 0; j < 32; j++) {
        float a = sb1[j];
        #pragma unroll
        for (int k = 0; k < 64; k++) a += x[k] * sW1[k * 32 + j];
        y[j] = fmaxf(a, 0.f);
    }
    float z[16];
    #pragma unroll
    for (int j = 0; j < 16; j++) {
        float a = sb2[j];
        #pragma unroll
        for (int k = 0; k < 32; k++) a += y[k] * sW2[k * 16 + j];
        z[j] = fmaxf(a, 0.f);
    }
    float o = sb3;
    #pragma unroll
    for (int k = 0; k < 16; k++) o += z[k] * sW3[k];
    out[g] = o;
}

// ---------------- launch ----------------
extern "C" void kernel_launch(void* const* d_in, const int* in_sizes, int n_in,
                              void* d_out, int out_size) {
    const int*   h         = (const int*)d_in[0];
    const int*   e         = (const int*)d_in[1];
    const int*   src       = (const int*)d_in[2];
    const int*   dst       = (const int*)d_in[3];
    const int*   graph_ids = (const int*)d_in[4];
    const float* node_emb  = (const float*)d_in[5];
    const float* edge_emb  = (const float*)d_in[6];
    const float* bn_h_g    = (const float*)d_in[7];
    const float* bn_h_b    = (const float*)d_in[8];
    const float* bn_e_g    = (const float*)d_in[9];
    const float* bn_e_b    = (const float*)d_in[10];
    const float* W1        = (const float*)d_in[11];
    const float* b1        = (const float*)d_in[12];
    const float* W2        = (const float*)d_in[13];
    const float* b2        = (const float*)d_in[14];
    const float* W3        = (const float*)d_in[15];
    const float* b3        = (const float*)d_in[16];
    float* out = (float*)d_out;

    const int NODE_WARP_BLOCKS = (N_NODES_C + 7) / 8;
    const int NL_BLOCKS = (N_NODES_C * 32 + 255) / 256;

    k_init<<<(N_NODES_C + 255) / 256, 256>>>();
    k_deg<<<(N_EDGES_C + 255) / 256, 256>>>(dst, graph_ids);
    k_nodeinit<<<NODE_WARP_BLOCKS, 256>>>(h, node_emb);
    k_scanA<<<N_TILES, SCAN_TILE>>>();
    k_scanB<<<1, 64>>>();
    k_scanC<<<N_TILES, SCAN_TILE>>>();
    k_permute<<<(N_EDGES_C + 255) / 256, 256>>>(e, src, dst, h);

    k_fused<0><<<NODE_WARP_BLOCKS, 256>>>(edge_emb, node_emb, bn_e_g, bn_e_b, bn_h_g, bn_h_b);
    k_fused<1><<<NODE_WARP_BLOCKS, 256>>>(edge_emb, node_emb, bn_e_g, bn_e_b, bn_h_g, bn_h_b);
    k_fused<2><<<NODE_WARP_BLOCKS, 256>>>(edge_emb, node_emb, bn_e_g, bn_e_b, bn_h_g, bn_h_b);
    k_fused<3><<<NODE_WARP_BLOCKS, 256>>>(edge_emb, node_emb, bn_e_g, bn_e_b, bn_h_g, bn_h_b);
    k_BhPool<<<NL_BLOCKS, 256>>>(graph_ids, bn_h_g, bn_h_b);

    k_mlp<<<1, 256>>>(W1, b1, W2, b2, W3, b3, out);
    (void)in_sizes; (void)n_in; (void)out_size;
}

// round 15
// speedup vs baseline: 1.0790x; 1.0790x over previous
#include <cuda_runtime.h>
#include <cuda_fp16.h>

#define N_NODES_C 50000
#define N_EDGES_C 800000
#define HID_C 64
#define N_GRAPHS_C 256
#define BN_EPS_C 1e-5f
#define GATE_EPS_C 1e-6f
#define SCAN_TILE 1024
#define N_TILES ((N_NODES_C + SCAN_TILE - 1) / SCAN_TILE)

// ---------------- persistent device scratch ----------------
__device__ float4 g_hfi[(size_t)N_NODES_C * 32];
__device__ __half2 g_efh[(size_t)N_EDGES_C * 32];  // edge features fp16 (dst-sorted)
__device__ float g_hpre[N_NODES_C * HID_C];        // pre-BN h_new
__device__ float g_norm[N_NODES_C];
__device__ int   g_deg[N_NODES_C];
__device__ int   g_cursor[N_NODES_C];
__device__ int   g_rowptr[N_NODES_C + 1];
__device__ int   g_srcs[N_EDGES_C];                // packed: src(16) | etype(2)<<16 | hidx(7)<<18
__device__ int   g_bsum[N_TILES];
__device__ int   g_boff[N_TILES];
__device__ float g_stats4[4][256];                 // per-layer [se, se2, sh, sh2]
__device__ float g_hg[N_GRAPHS_C * HID_C];
__device__ int   g_gcount[N_GRAPHS_C];

// ---- streaming (evict-first) access helpers for the big ef array ----
__device__ __forceinline__ unsigned long long mk_policy() {
    unsigned long long p;
    asm volatile("createpolicy.fractional.L2::evict_first.b64 %0, 1.0;" : "=l"(p));
    return p;
}
__device__ __forceinline__ unsigned ld_stream_b32(const void* ptr, unsigned long long pol) {
    unsigned v;
    asm volatile("ld.global.L2::cache_hint.b32 %0, [%1], %2;"
                 : "=r"(v) : "l"(ptr), "l"(pol));
    return v;
}
__device__ __forceinline__ void st_stream_b32(void* ptr, unsigned v, unsigned long long pol) {
    asm volatile("st.global.L2::cache_hint.b32 [%0], %1, %2;"
                 :: "l"(ptr), "r"(v), "l"(pol));
}

// sigmoid via single-MUFU hardware tanh: sigma(x) = 0.5*tanh(x/2) + 0.5
__device__ __forceinline__ float fast_sigmoid(float x) {
    float t;
    asm("tanh.approx.f32 %0, %1;" : "=f"(t) : "f"(x * 0.5f));
    return fmaf(t, 0.5f, 0.5f);
}

// BN scale/shift for one feature from raw sums
__device__ __forceinline__ void bn_coeff(float s, float s2, float invN,
                                         float gamma, float beta,
                                         float& scale, float& shift) {
    float mu = s * invN;
    float var = s2 * invN - mu * mu;
    scale = gamma * rsqrtf(var + BN_EPS_C);
    shift = beta - mu * scale;
}

// ---------------- prep kernels (R9/R12-proven structure) ----------------

__global__ void k_init() {
    int i = blockIdx.x * blockDim.x + threadIdx.x;
    if (i < N_NODES_C) { g_deg[i] = 0; g_cursor[i] = 0; }
    if (i < N_GRAPHS_C * HID_C) g_hg[i] = 0.f;
    if (i < N_GRAPHS_C) g_gcount[i] = 0;
    if (i < 4 * 256) ((float*)g_stats4)[i] = 0.f;
}

__global__ void k_deg(const int* __restrict__ dst, const int* __restrict__ graph_ids) {
    int i = blockIdx.x * blockDim.x + threadIdx.x;
    if (i < N_EDGES_C) atomicAdd(&g_deg[dst[i]], 1);
    if (i < N_NODES_C) atomicAdd(&g_gcount[graph_ids[i]], 1);
}

__global__ void k_nodeinit(const int* __restrict__ h, const float* __restrict__ node_emb) {
    int tid = threadIdx.x;
    int warp = tid >> 5, lane = tid & 31;
    int n = blockIdx.x * 8 + warp;
    if (n >= N_NODES_C) return;
    if (lane == 0) g_norm[n] = rsqrtf(fmaxf((float)g_deg[n], 1.f));
    int hi = h[n];
    float2 v = *(const float2*)(node_emb + hi * HID_C + 2 * lane);
    g_hfi[(size_t)n * 32 + lane] = make_float4(v.x, v.y, v.x, v.y);
}

__global__ void k_scanA() {
    __shared__ int s[32];
    int b = blockIdx.x, tid = threadIdx.x;
    int i = b * SCAN_TILE + tid;
    int v = (i < N_NODES_C) ? g_deg[i] : 0;
    #pragma unroll
    for (int off = 16; off > 0; off >>= 1) v += __shfl_down_sync(0xFFFFFFFFu, v, off);
    if ((tid & 31) == 0) s[tid >> 5] = v;
    __syncthreads();
    if (tid < 32) {
        int w = s[tid];
        #pragma unroll
        for (int off = 16; off > 0; off >>= 1) w += __shfl_down_sync(0xFFFFFFFFu, w, off);
        if (tid == 0) g_bsum[b] = w;
    }
}

__global__ void k_scanB() {
    int tid = threadIdx.x;
    int v = (tid < N_TILES) ? g_bsum[tid] : 0;
    int x = v;
    #pragma unroll
    for (int off = 1; off < 64; off <<= 1) {
        int t = __shfl_up_sync(0xFFFFFFFFu, x, off);
        if ((tid & 31) >= off) x += t;
    }
    __shared__ int s_half;
    if (tid == 31) s_half = x;
    __syncthreads();
    if (tid >= 32) x += s_half;
    if (tid < N_TILES) g_boff[tid] = x - v;
}

__global__ void k_scanC() {
    __shared__ int s_warp[32];
    int b = blockIdx.x, tid = threadIdx.x;
    int lane = tid & 31, warp = tid >> 5;
    int i = b * SCAN_TILE + tid;
    int v = (i < N_NODES_C) ? g_deg[i] : 0;
    int x = v;
    #pragma unroll
    for (int off = 1; off < 32; off <<= 1) {
        int t = __shfl_up_sync(0xFFFFFFFFu, x, off);
        if (lane >= off) x += t;
    }
    if (lane == 31) s_warp[warp] = x;
    __syncthreads();
    if (warp == 0) {
        int w = s_warp[lane];
        #pragma unroll
        for (int off = 1; off < 32; off <<= 1) {
            int t = __shfl_up_sync(0xFFFFFFFFu, w, off);
            if (lane >= off) w += t;
        }
        s_warp[lane] = w;
    }
    __syncthreads();
    int incl = x + (warp > 0 ? s_warp[warp - 1] : 0) + g_boff[b];
    if (i < N_NODES_C) g_rowptr[i + 1] = incl;
    if (b == 0 && tid == 0) g_rowptr[0] = 0;
}

// counting-sort permute; packs src | etype<<16 | h[src]<<18
__global__ void k_permute(const int* __restrict__ e, const int* __restrict__ src,
                          const int* __restrict__ dst, const int* __restrict__ h) {
    int i = blockIdx.x * blockDim.x + threadIdx.x;
    if (i >= N_EDGES_C) return;
    int d = dst[i];
    int s = src[i];
    int pos = g_rowptr[d] + atomicAdd(&g_cursor[d], 1);
    g_srcs[pos] = s | (e[i] << 16) | (h[s] << 18);
}

// ---------------- fused layer pass ----------------
// 1 warp/node, 4-wide batches, shallow pipeline (R12-proven loop shape).
// min 3 blocks/SM to raise resident warps 16 -> 24 (occupancy A/B vs R12).
template<int L>
__global__ void __launch_bounds__(256, 3) k_fused(const float* __restrict__ edge_emb,
                                                  const float* __restrict__ node_emb,
                                                  const float* __restrict__ beg_,
                                                  const float* __restrict__ beb) {
    __shared__ float s_emb[4 * HID_C];
    __shared__ float s_acc[256];
    int tid = threadIdx.x;
    if (L <= 1) s_emb[tid] = edge_emb[tid];
    s_acc[tid] = 0.f;
    __syncthreads();
    int warp = tid >> 5, lane = tid & 31;
    int n = blockIdx.x * 8 + warp;
    if (n < N_NODES_C) {
        unsigned long long pol = mk_policy();
        float4 f4 = g_hfi[(size_t)n * 32 + lane];
        float hdcx = f4.x, hdcy = f4.y, hdpx = f4.z, hdpy = f4.w;
        float sce_x = 0.f, sce_y = 0.f, she_x = 0.f, she_y = 0.f;
        if (L >= 1) {
            const float* st = g_stats4[L - 1];
            const float invE = 1.f / (float)N_EDGES_C;
            int f0 = 2 * lane, f1 = 2 * lane + 1;
            bn_coeff(st[f0], st[64 + f0], invE,
                     __ldg(beg_ + (L - 1) * HID_C + f0), __ldg(beb + (L - 1) * HID_C + f0),
                     sce_x, she_x);
            bn_coeff(st[f1], st[64 + f1], invE,
                     __ldg(beg_ + (L - 1) * HID_C + f1), __ldg(beb + (L - 1) * HID_C + f1),
                     sce_y, she_y);
        }
        float nn = g_norm[n];
        float mx = 0.f, my = 0.f, dx = 0.f, dy = 0.f;
        float sex = 0.f, sey = 0.f, se2x = 0.f, se2y = 0.f;
        int beg = g_rowptr[n], end = g_rowptr[n + 1];
        int nb = (end - beg) >> 2;              // full 4-edge batches

        auto fetch_nf = [&](int sp, float2& nc, float2& np) {
            int s = sp & 0xFFFF;
            if (L == 0) {
                int hidx = (sp >> 18) & 0x7F;
                nc = __ldg((const float2*)(node_emb + hidx * HID_C + 2 * lane));
                np = make_float2(0.f, 0.f);
            } else if (L == 1) {
                nc = *(const float2*)&g_hfi[(size_t)s * 32 + lane];   // cur half (8B)
                int hidx = (sp >> 18) & 0x7F;
                np = __ldg((const float2*)(node_emb + hidx * HID_C + 2 * lane));
            } else {
                float4 v = g_hfi[(size_t)s * 32 + lane];
                nc = make_float2(v.x, v.y);
                np = make_float2(v.z, v.w);
            }
        };

        auto compute = [&](int k, float2 nc, float2 np, float ns, float rawx, float rawy) {
            float efx, efy;
            if (L == 0) {
                efx = rawx; efy = rawy;
            } else {
                float epx = np.x + hdpx + rawx;
                float epy = np.y + hdpy + rawy;
                efx = rawx + fmaxf(epx * sce_x + she_x, 0.f);
                efy = rawy + fmaxf(epy * sce_y + she_y, 0.f);
                if (L < 3) {
                    __half2 hv = __floats2half2_rn(efx, efy);
                    st_stream_b32(&g_efh[(size_t)k * 32 + lane], *(unsigned*)&hv, pol);
                }
            }
            float ex = nc.x + hdcx + efx;
            float ey = nc.y + hdcy + efy;
            float sgx = fast_sigmoid(ex);
            float sgy = fast_sigmoid(ey);
            mx += sgx * nc.x * ns; my += sgy * nc.y * ns;
            dx += sgx; dy += sgy;
            if (L < 3) { sex += ex; sey += ey; se2x += ex * ex; se2y += ey * ey; }
        };

        // ---- shallow software pipeline on the sequential streams ----
        int spA[4], spB[4];
        unsigned efA[4], efB[4];
        if (nb > 0) {
            #pragma unroll
            for (int j = 0; j < 4; j++) spA[j] = g_srcs[beg + j];
            if (L >= 2) {
                #pragma unroll
                for (int j = 0; j < 4; j++)
                    efA[j] = ld_stream_b32(&g_efh[(size_t)(beg + j) * 32 + lane], pol);
            }
        }
        for (int b = 0; b < nb; b++) {
            int kk = beg + b * 4;
            if (b + 1 < nb) {
                #pragma unroll
                for (int j = 0; j < 4; j++) spB[j] = g_srcs[kk + 4 + j];
                if (L >= 2) {
                    #pragma unroll
                    for (int j = 0; j < 4; j++)
                        efB[j] = ld_stream_b32(&g_efh[(size_t)(kk + 4 + j) * 32 + lane], pol);
                }
            }
            float2 nc[4], np[4];
            #pragma unroll
            for (int j = 0; j < 4; j++) fetch_nf(spA[j], nc[j], np[j]);
            float ns[4];
            #pragma unroll
            for (int j = 0; j < 4; j++) ns[j] = g_norm[spA[j] & 0xFFFF];
            float rawx[4], rawy[4];
            #pragma unroll
            for (int j = 0; j < 4; j++) {
                if (L <= 1) {
                    int et = (spA[j] >> 16) & 3;
                    rawx[j] = s_emb[et * HID_C + 2 * lane];
                    rawy[j] = s_emb[et * HID_C + 2 * lane + 1];
                } else {
                    float2 r = __half22float2(*(__half2*)&efA[j]);
                    rawx[j] = r.x; rawy[j] = r.y;
                }
            }
            #pragma unroll
            for (int j = 0; j < 4; j++) compute(kk + j, nc[j], np[j], ns[j], rawx[j], rawy[j]);
            #pragma unroll
            for (int j = 0; j < 4; j++) { spA[j] = spB[j]; efA[j] = efB[j]; }
        }
        // tail
        for (int k = beg + nb * 4; k < end; k++) {
            int sp = g_srcs[k];
            float2 nc, np;
            fetch_nf(sp, nc, np);
            float ns = g_norm[sp & 0xFFFF];
            float rawx, rawy;
            if (L <= 1) {
                int et = (sp >> 16) & 3;
                rawx = s_emb[et * HID_C + 2 * lane];
                rawy = s_emb[et * HID_C + 2 * lane + 1];
            } else {
                unsigned u = ld_stream_b32(&g_efh[(size_t)k * 32 + lane], pol);
                float2 r = __half22float2(*(__half2*)&u);
                rawx = r.x; rawy = r.y;
            }
            compute(k, nc, np, ns, rawx, rawy);
        }

        float hpx = (hdcx * nn + mx / (dx + GATE_EPS_C)) * nn;
        float hpy = (hdcy * nn + my / (dy + GATE_EPS_C)) * nn;
        *(float2*)(&g_hpre[n * HID_C + 2 * lane]) = make_float2(hpx, hpy);
        if (L < 3) {
            atomicAdd(&s_acc[2 * lane], sex);
            atomicAdd(&s_acc[2 * lane + 1], sey);
            atomicAdd(&s_acc[64 + 2 * lane], se2x);
            atomicAdd(&s_acc[64 + 2 * lane + 1], se2y);
        }
        atomicAdd(&s_acc[128 + 2 * lane], hpx);
        atomicAdd(&s_acc[128 + 2 * lane + 1], hpy);
        atomicAdd(&s_acc[192 + 2 * lane], hpx * hpx);
        atomicAdd(&s_acc[192 + 2 * lane + 1], hpy * hpy);
    }
    __syncthreads();
    atomicAdd(&g_stats4[L][tid], s_acc[tid]);
}

// node update: (cur, prev) -> (cur + relu(BN_l(hpre)), cur); BN coeffs from g_stats4[l]
__global__ void k_Bh(int l, const float* __restrict__ bhg, const float* __restrict__ bhb) {
    int i = blockIdx.x * blockDim.x + threadIdx.x;
    if (i >= N_NODES_C * 32) return;
    int lane = i & 31;
    const float* st = g_stats4[l];
    const float invN = 1.f / (float)N_NODES_C;
    int f0 = 2 * lane, f1 = 2 * lane + 1;
    float scx, shx, scy, shy;
    bn_coeff(st[128 + f0], st[192 + f0], invN,
             __ldg(bhg + l * HID_C + f0), __ldg(bhb + l * HID_C + f0), scx, shx);
    bn_coeff(st[128 + f1], st[192 + f1], invN,
             __ldg(bhg + l * HID_C + f1), __ldg(bhb + l * HID_C + f1), scy, shy);
    float4 f4 = g_hfi[i];
    float2 hp = *(const float2*)(&g_hpre[i * 2]);
    float vx = fmaxf(hp.x * scx + shx, 0.f);
    float vy = fmaxf(hp.y * scy + shy, 0.f);
    g_hfi[i] = make_float4(f4.x + vx, f4.y + vy, f4.x, f4.y);
}

// final node update (layer 3) fused with per-graph sum pooling
__global__ void k_BhPool(const int* __restrict__ graph_ids,
                         const float* __restrict__ bhg, const float* __restrict__ bhb) {
    int i = blockIdx.x * blockDim.x + threadIdx.x;
    if (i >= N_NODES_C * 32) return;
    int lane = i & 31;
    int n = i >> 5;
    const float* st = g_stats4[3];
    const float invN = 1.f / (float)N_NODES_C;
    int f0 = 2 * lane, f1 = 2 * lane + 1;
    float scx, shx, scy, shy;
    bn_coeff(st[128 + f0], st[192 + f0], invN,
             __ldg(bhg + 3 * HID_C + f0), __ldg(bhb + 3 * HID_C + f0), scx, shx);
    bn_coeff(st[128 + f1], st[192 + f1], invN,
             __ldg(bhg + 3 * HID_C + f1), __ldg(bhb + 3 * HID_C + f1), scy, shy);
    float4 f4 = g_hfi[i];
    float2 hp = *(const float2*)(&g_hpre[i * 2]);
    float vx = f4.x + fmaxf(hp.x * scx + shx, 0.f);
    float vy = f4.y + fmaxf(hp.y * scy + shy, 0.f);
    int g = graph_ids[n];
    atomicAdd(&g_hg[(g << 6) + f0], vx);
    atomicAdd(&g_hg[(g << 6) + f1], vy);
}

// final 3-layer MLP, one thread per graph
__global__ void k_mlp(const float* __restrict__ W1, const float* __restrict__ b1,
                      const float* __restrict__ W2, const float* __restrict__ b2,
                      const float* __restrict__ W3, const float* __restrict__ b3,
                      float* __restrict__ out) {
    __shared__ float sW1[64 * 32], sW2[32 * 16], sb1[32], sb2[16], sW3[16], sb3;
    int tid = threadIdx.x;
    for (int i = tid; i < 64 * 32; i += 256) sW1[i] = W1[i];
    for (int i = tid; i < 32 * 16; i += 256) sW2[i] = W2[i];
    if (tid < 32) sb1[tid] = b1[tid];
    if (tid < 16) { sb2[tid] = b2[tid]; sW3[tid] = W3[tid]; }
    if (tid == 0) sb3 = b3[0];
    __syncthreads();
    int g = tid;
    float inv = 1.f / fmaxf((float)g_gcount[g], 1.f);
    float x[64];
    #pragma unroll
    for (int k = 0; k < 64; k++) x[k] = g_hg[g * 64 + k] * inv;
    float y[32];
    #pragma unroll
    for (int j = 0; j < 32; j++) {
        float a = sb1[j];
        #pragma unroll
        for (int k = 0; k < 64; k++) a += x[k] * sW1[k * 32 + j];
        y[j] = fmaxf(a, 0.f);
    }
    float z[16];
    #pragma unroll
    for (int j = 0; j < 16; j++) {
        float a = sb2[j];
        #pragma unroll
        for (int k = 0; k < 32; k++) a += y[k] * sW2[k * 16 + j];
        z[j] = fmaxf(a, 0.f);
    }
    float o = sb3;
    #pragma unroll
    for (int k = 0; k < 16; k++) o += z[k] * sW3[k];
    out[g] = o;
}

// ---------------- launch ----------------
extern "C" void kernel_launch(void* const* d_in, const int* in_sizes, int n_in,
                              void* d_out, int out_size) {
    const int*   h         = (const int*)d_in[0];
    const int*   e         = (const int*)d_in[1];
    const int*   src       = (const int*)d_in[2];
    const int*   dst       = (const int*)d_in[3];
    const int*   graph_ids = (const int*)d_in[4];
    const float* node_emb  = (const float*)d_in[5];
    const float* edge_emb  = (const float*)d_in[6];
    const float* bn_h_g    = (const float*)d_in[7];
    const float* bn_h_b    = (const float*)d_in[8];
    const float* bn_e_g    = (const float*)d_in[9];
    const float* bn_e_b    = (const float*)d_in[10];
    const float* W1        = (const float*)d_in[11];
    const float* b1        = (const float*)d_in[12];
    const float* W2        = (const float*)d_in[13];
    const float* b2        = (const float*)d_in[14];
    const float* W3        = (const float*)d_in[15];
    const float* b3        = (const float*)d_in[16];
    float* out = (float*)d_out;

    const int NODE_WARP_BLOCKS = (N_NODES_C + 7) / 8;
    const int NL_BLOCKS = (N_NODES_C * 32 + 255) / 256;

    k_init<<<(N_NODES_C + 255) / 256, 256>>>();
    k_deg<<<(N_EDGES_C + 255) / 256, 256>>>(dst, graph_ids);
    k_nodeinit<<<NODE_WARP_BLOCKS, 256>>>(h, node_emb);
    k_scanA<<<N_TILES, SCAN_TILE>>>();
    k_scanB<<<1, 64>>>();
    k_scanC<<<N_TILES, SCAN_TILE>>>();
    k_permute<<<(N_EDGES_C + 255) / 256, 256>>>(e, src, dst, h);

    k_fused<0><<<NODE_WARP_BLOCKS, 256>>>(edge_emb, node_emb, bn_e_g, bn_e_b);
    k_Bh<<<NL_BLOCKS, 256>>>(0, bn_h_g, bn_h_b);
    k_fused<1><<<NODE_WARP_BLOCKS, 256>>>(edge_emb, node_emb, bn_e_g, bn_e_b);
    k_Bh<<<NL_BLOCKS, 256>>>(1, bn_h_g, bn_h_b);
    k_fused<2><<<NODE_WARP_BLOCKS, 256>>>(edge_emb, node_emb, bn_e_g, bn_e_b);
    k_Bh<<<NL_BLOCKS, 256>>>(2, bn_h_g, bn_h_b);
    k_fused<3><<<NODE_WARP_BLOCKS, 256>>>(edge_emb, node_emb, bn_e_g, bn_e_b);
    k_BhPool<<<NL_BLOCKS, 256>>>(graph_ids, bn_h_g, bn_h_b);

    k_mlp<<<1, 256>>>(W1, b1, W2, b2, W3, b3, out);
    (void)in_sizes; (void)n_in; (void)out_size;
}

// round 16
// speedup vs baseline: 1.0941x; 1.0140x over previous
#include <cuda_runtime.h>
#include <cuda_fp16.h>

#define N_NODES_C 50000
#define N_EDGES_C 800000
#define HID_C 64
#define N_GRAPHS_C 256
#define BN_EPS_C 1e-5f
#define GATE_EPS_C 1e-6f
#define SCAN_TILE 1024
#define N_TILES ((N_NODES_C + SCAN_TILE - 1) / SCAN_TILE)

// ---------------- persistent device scratch ----------------
__device__ float4 g_hfi[(size_t)N_NODES_C * 32];
__device__ __half2 g_efh[(size_t)N_EDGES_C * 32];  // edge features fp16 (dst-sorted)
__device__ float g_hpre[N_NODES_C * HID_C];        // pre-BN h_new
__device__ float g_norm[N_NODES_C];
__device__ int   g_deg[N_NODES_C];
__device__ int   g_cursor[N_NODES_C];
__device__ int   g_rowptr[N_NODES_C + 1];
__device__ int   g_srcs[N_EDGES_C];                // packed: src(16) | etype(2)<<16 | hidx(7)<<18
__device__ int   g_bsum[N_TILES];
__device__ int   g_boff[N_TILES];
__device__ float g_stats4[4][256];                 // per-layer [se, se2, sh, sh2]
__device__ float g_hg[N_GRAPHS_C * HID_C];
__device__ int   g_gcount[N_GRAPHS_C];

// ---- streaming (evict-first) access helpers for the big ef array ----
__device__ __forceinline__ unsigned long long mk_policy() {
    unsigned long long p;
    asm volatile("createpolicy.fractional.L2::evict_first.b64 %0, 1.0;" : "=l"(p));
    return p;
}
__device__ __forceinline__ unsigned ld_stream_b32(const void* ptr, unsigned long long pol) {
    unsigned v;
    asm volatile("ld.global.L2::cache_hint.b32 %0, [%1], %2;"
                 : "=r"(v) : "l"(ptr), "l"(pol));
    return v;
}
__device__ __forceinline__ void st_stream_b32(void* ptr, unsigned v, unsigned long long pol) {
    asm volatile("st.global.L2::cache_hint.b32 [%0], %1, %2;"
                 :: "l"(ptr), "r"(v), "l"(pol));
}

// sigmoid via single-MUFU hardware tanh: sigma(x) = 0.5*tanh(x/2) + 0.5
__device__ __forceinline__ float fast_sigmoid(float x) {
    float t;
    asm("tanh.approx.f32 %0, %1;" : "=f"(t) : "f"(x * 0.5f));
    return fmaf(t, 0.5f, 0.5f);
}

// BN scale/shift for one feature from raw sums
__device__ __forceinline__ void bn_coeff(float s, float s2, float invN,
                                         float gamma, float beta,
                                         float& scale, float& shift) {
    float mu = s * invN;
    float var = s2 * invN - mu * mu;
    scale = gamma * rsqrtf(var + BN_EPS_C);
    shift = beta - mu * scale;
}

// ---------------- prep kernels (R9/R12-proven structure) ----------------

__global__ void k_init() {
    int i = blockIdx.x * blockDim.x + threadIdx.x;
    if (i < N_NODES_C) { g_deg[i] = 0; g_cursor[i] = 0; }
    if (i < N_GRAPHS_C * HID_C) g_hg[i] = 0.f;
    if (i < N_GRAPHS_C) g_gcount[i] = 0;
    if (i < 4 * 256) ((float*)g_stats4)[i] = 0.f;
}

__global__ void k_deg(const int* __restrict__ dst, const int* __restrict__ graph_ids) {
    int i = blockIdx.x * blockDim.x + threadIdx.x;
    if (i < N_EDGES_C) atomicAdd(&g_deg[dst[i]], 1);
    if (i < N_NODES_C) atomicAdd(&g_gcount[graph_ids[i]], 1);
}

__global__ void k_nodeinit(const int* __restrict__ h, const float* __restrict__ node_emb) {
    int tid = threadIdx.x;
    int warp = tid >> 5, lane = tid & 31;
    int n = blockIdx.x * 8 + warp;
    if (n >= N_NODES_C) return;
    if (lane == 0) g_norm[n] = rsqrtf(fmaxf((float)g_deg[n], 1.f));
    int hi = h[n];
    float2 v = *(const float2*)(node_emb + hi * HID_C + 2 * lane);
    g_hfi[(size_t)n * 32 + lane] = make_float4(v.x, v.y, v.x, v.y);
}

__global__ void k_scanA() {
    __shared__ int s[32];
    int b = blockIdx.x, tid = threadIdx.x;
    int i = b * SCAN_TILE + tid;
    int v = (i < N_NODES_C) ? g_deg[i] : 0;
    #pragma unroll
    for (int off = 16; off > 0; off >>= 1) v += __shfl_down_sync(0xFFFFFFFFu, v, off);
    if ((tid & 31) == 0) s[tid >> 5] = v;
    __syncthreads();
    if (tid < 32) {
        int w = s[tid];
        #pragma unroll
        for (int off = 16; off > 0; off >>= 1) w += __shfl_down_sync(0xFFFFFFFFu, w, off);
        if (tid == 0) g_bsum[b] = w;
    }
}

__global__ void k_scanB() {
    int tid = threadIdx.x;
    int v = (tid < N_TILES) ? g_bsum[tid] : 0;
    int x = v;
    #pragma unroll
    for (int off = 1; off < 64; off <<= 1) {
        int t = __shfl_up_sync(0xFFFFFFFFu, x, off);
        if ((tid & 31) >= off) x += t;
    }
    __shared__ int s_half;
    if (tid == 31) s_half = x;
    __syncthreads();
    if (tid >= 32) x += s_half;
    if (tid < N_TILES) g_boff[tid] = x - v;
}

__global__ void k_scanC() {
    __shared__ int s_warp[32];
    int b = blockIdx.x, tid = threadIdx.x;
    int lane = tid & 31, warp = tid >> 5;
    int i = b * SCAN_TILE + tid;
    int v = (i < N_NODES_C) ? g_deg[i] : 0;
    int x = v;
    #pragma unroll
    for (int off = 1; off < 32; off <<= 1) {
        int t = __shfl_up_sync(0xFFFFFFFFu, x, off);
        if (lane >= off) x += t;
    }
    if (lane == 31) s_warp[warp] = x;
    __syncthreads();
    if (warp == 0) {
        int w = s_warp[lane];
        #pragma unroll
        for (int off = 1; off < 32; off <<= 1) {
            int t = __shfl_up_sync(0xFFFFFFFFu, w, off);
            if (lane >= off) w += t;
        }
        s_warp[lane] = w;
    }
    __syncthreads();
    int incl = x + (warp > 0 ? s_warp[warp - 1] : 0) + g_boff[b];
    if (i < N_NODES_C) g_rowptr[i + 1] = incl;
    if (b == 0 && tid == 0) g_rowptr[0] = 0;
}

// counting-sort permute; packs src | etype<<16 | h[src]<<18
__global__ void k_permute(const int* __restrict__ e, const int* __restrict__ src,
                          const int* __restrict__ dst, const int* __restrict__ h) {
    int i = blockIdx.x * blockDim.x + threadIdx.x;
    if (i >= N_EDGES_C) return;
    int d = dst[i];
    int s = src[i];
    int pos = g_rowptr[d] + atomicAdd(&g_cursor[d], 1);
    g_srcs[pos] = s | (e[i] << 16) | (h[s] << 18);
}

// ---------------- fused layer pass ----------------
// 1 warp/node, 4-wide batched gathers (MLP=4), NO sp/ef double-buffer —
// registers traded for occupancy: min 4 blocks/SM (32 resident warps).
template<int L>
__global__ void __launch_bounds__(256, 4) k_fused(const float* __restrict__ edge_emb,
                                                  const float* __restrict__ node_emb,
                                                  const float* __restrict__ beg_,
                                                  const float* __restrict__ beb) {
    __shared__ float s_emb[4 * HID_C];
    __shared__ float s_acc[256];
    int tid = threadIdx.x;
    if (L <= 1) s_emb[tid] = edge_emb[tid];
    s_acc[tid] = 0.f;
    __syncthreads();
    int warp = tid >> 5, lane = tid & 31;
    int n = blockIdx.x * 8 + warp;
    if (n < N_NODES_C) {
        unsigned long long pol = mk_policy();
        float4 f4 = g_hfi[(size_t)n * 32 + lane];
        float hdcx = f4.x, hdcy = f4.y, hdpx = f4.z, hdpy = f4.w;
        float sce_x = 0.f, sce_y = 0.f, she_x = 0.f, she_y = 0.f;
        if (L >= 1) {
            const float* st = g_stats4[L - 1];
            const float invE = 1.f / (float)N_EDGES_C;
            int f0 = 2 * lane, f1 = 2 * lane + 1;
            bn_coeff(st[f0], st[64 + f0], invE,
                     __ldg(beg_ + (L - 1) * HID_C + f0), __ldg(beb + (L - 1) * HID_C + f0),
                     sce_x, she_x);
            bn_coeff(st[f1], st[64 + f1], invE,
                     __ldg(beg_ + (L - 1) * HID_C + f1), __ldg(beb + (L - 1) * HID_C + f1),
                     sce_y, she_y);
        }
        float nn = g_norm[n];
        float mx = 0.f, my = 0.f, dx = 0.f, dy = 0.f;
        float sex = 0.f, sey = 0.f, se2x = 0.f, se2y = 0.f;
        int beg = g_rowptr[n], end = g_rowptr[n + 1];

        auto fetch_nf = [&](int sp, float2& nc, float2& np) {
            int s = sp & 0xFFFF;
            if (L == 0) {
                int hidx = (sp >> 18) & 0x7F;
                nc = __ldg((const float2*)(node_emb + hidx * HID_C + 2 * lane));
                np = make_float2(0.f, 0.f);
            } else if (L == 1) {
                nc = *(const float2*)&g_hfi[(size_t)s * 32 + lane];   // cur half (8B)
                int hidx = (sp >> 18) & 0x7F;
                np = __ldg((const float2*)(node_emb + hidx * HID_C + 2 * lane));
            } else {
                float4 v = g_hfi[(size_t)s * 32 + lane];
                nc = make_float2(v.x, v.y);
                np = make_float2(v.z, v.w);
            }
        };

        auto compute = [&](int k, float2 nc, float2 np, float ns, float rawx, float rawy) {
            float efx, efy;
            if (L == 0) {
                efx = rawx; efy = rawy;
            } else {
                float epx = np.x + hdpx + rawx;
                float epy = np.y + hdpy + rawy;
                efx = rawx + fmaxf(epx * sce_x + she_x, 0.f);
                efy = rawy + fmaxf(epy * sce_y + she_y, 0.f);
                if (L < 3) {
                    __half2 hv = __floats2half2_rn(efx, efy);
                    st_stream_b32(&g_efh[(size_t)k * 32 + lane], *(unsigned*)&hv, pol);
                }
            }
            float ex = nc.x + hdcx + efx;
            float ey = nc.y + hdcy + efy;
            float sgx = fast_sigmoid(ex);
            float sgy = fast_sigmoid(ey);
            mx += sgx * nc.x * ns; my += sgy * nc.y * ns;
            dx += sgx; dy += sgy;
            if (L < 3) { sex += ex; sey += ey; se2x += ex * ex; se2y += ey * ey; }
        };

        int k = beg;
        for (; k + 3 < end; k += 4) {
            int sp[4];
            #pragma unroll
            for (int j = 0; j < 4; j++) sp[j] = g_srcs[k + j];
            float2 nc[4], np[4];
            #pragma unroll
            for (int j = 0; j < 4; j++) fetch_nf(sp[j], nc[j], np[j]);
            float ns[4];
            #pragma unroll
            for (int j = 0; j < 4; j++) ns[j] = g_norm[sp[j] & 0xFFFF];
            float rawx[4], rawy[4];
            #pragma unroll
            for (int j = 0; j < 4; j++) {
                if (L <= 1) {
                    int et = (sp[j] >> 16) & 3;
                    rawx[j] = s_emb[et * HID_C + 2 * lane];
                    rawy[j] = s_emb[et * HID_C + 2 * lane + 1];
                } else {
                    unsigned u = ld_stream_b32(&g_efh[(size_t)(k + j) * 32 + lane], pol);
                    float2 r = __half22float2(*(__half2*)&u);
                    rawx[j] = r.x; rawy[j] = r.y;
                }
            }
            #pragma unroll
            for (int j = 0; j < 4; j++) compute(k + j, nc[j], np[j], ns[j], rawx[j], rawy[j]);
        }
        for (; k < end; k++) {
            int sp = g_srcs[k];
            float2 nc, np;
            fetch_nf(sp, nc, np);
            float ns = g_norm[sp & 0xFFFF];
            float rawx, rawy;
            if (L <= 1) {
                int et = (sp >> 16) & 3;
                rawx = s_emb[et * HID_C + 2 * lane];
                rawy = s_emb[et * HID_C + 2 * lane + 1];
            } else {
                unsigned u = ld_stream_b32(&g_efh[(size_t)k * 32 + lane], pol);
                float2 r = __half22float2(*(__half2*)&u);
                rawx = r.x; rawy = r.y;
            }
            compute(k, nc, np, ns, rawx, rawy);
        }

        float hpx = (hdcx * nn + mx / (dx + GATE_EPS_C)) * nn;
        float hpy = (hdcy * nn + my / (dy + GATE_EPS_C)) * nn;
        *(float2*)(&g_hpre[n * HID_C + 2 * lane]) = make_float2(hpx, hpy);
        if (L < 3) {
            atomicAdd(&s_acc[2 * lane], sex);
            atomicAdd(&s_acc[2 * lane + 1], sey);
            atomicAdd(&s_acc[64 + 2 * lane], se2x);
            atomicAdd(&s_acc[64 + 2 * lane + 1], se2y);
        }
        atomicAdd(&s_acc[128 + 2 * lane], hpx);
        atomicAdd(&s_acc[128 + 2 * lane + 1], hpy);
        atomicAdd(&s_acc[192 + 2 * lane], hpx * hpx);
        atomicAdd(&s_acc[192 + 2 * lane + 1], hpy * hpy);
    }
    __syncthreads();
    atomicAdd(&g_stats4[L][tid], s_acc[tid]);
}

// node update: (cur, prev) -> (cur + relu(BN_l(hpre)), cur); BN coeffs from g_stats4[l]
__global__ void k_Bh(int l, const float* __restrict__ bhg, const float* __restrict__ bhb) {
    int i = blockIdx.x * blockDim.x + threadIdx.x;
    if (i >= N_NODES_C * 32) return;
    int lane = i & 31;
    const float* st = g_stats4[l];
    const float invN = 1.f / (float)N_NODES_C;
    int f0 = 2 * lane, f1 = 2 * lane + 1;
    float scx, shx, scy, shy;
    bn_coeff(st[128 + f0], st[192 + f0], invN,
             __ldg(bhg + l * HID_C + f0), __ldg(bhb + l * HID_C + f0), scx, shx);
    bn_coeff(st[128 + f1], st[192 + f1], invN,
             __ldg(bhg + l * HID_C + f1), __ldg(bhb + l * HID_C + f1), scy, shy);
    float4 f4 = g_hfi[i];
    float2 hp = *(const float2*)(&g_hpre[i * 2]);
    float vx = fmaxf(hp.x * scx + shx, 0.f);
    float vy = fmaxf(hp.y * scy + shy, 0.f);
    g_hfi[i] = make_float4(f4.x + vx, f4.y + vy, f4.x, f4.y);
}

// final node update (layer 3) fused with per-graph sum pooling
__global__ void k_BhPool(const int* __restrict__ graph_ids,
                         const float* __restrict__ bhg, const float* __restrict__ bhb) {
    int i = blockIdx.x * blockDim.x + threadIdx.x;
    if (i >= N_NODES_C * 32) return;
    int lane = i & 31;
    int n = i >> 5;
    const float* st = g_stats4[3];
    const float invN = 1.f / (float)N_NODES_C;
    int f0 = 2 * lane, f1 = 2 * lane + 1;
    float scx, shx, scy, shy;
    bn_coeff(st[128 + f0], st[192 + f0], invN,
             __ldg(bhg + 3 * HID_C + f0), __ldg(bhb + 3 * HID_C + f0), scx, shx);
    bn_coeff(st[128 + f1], st[192 + f1], invN,
             __ldg(bhg + 3 * HID_C + f1), __ldg(bhb + 3 * HID_C + f1), scy, shy);
    float4 f4 = g_hfi[i];
    float2 hp = *(const float2*)(&g_hpre[i * 2]);
    float vx = f4.x + fmaxf(hp.x * scx + shx, 0.f);
    float vy = f4.y + fmaxf(hp.y * scy + shy, 0.f);
    int g = graph_ids[n];
    atomicAdd(&g_hg[(g << 6) + f0], vx);
    atomicAdd(&g_hg[(g << 6) + f1], vy);
}

// final 3-layer MLP, one thread per graph
__global__ void k_mlp(const float* __restrict__ W1, const float* __restrict__ b1,
                      const float* __restrict__ W2, const float* __restrict__ b2,
                      const float* __restrict__ W3, const float* __restrict__ b3,
                      float* __restrict__ out) {
    __shared__ float sW1[64 * 32], sW2[32 * 16], sb1[32], sb2[16], sW3[16], sb3;
    int tid = threadIdx.x;
    for (int i = tid; i < 64 * 32; i += 256) sW1[i] = W1[i];
    for (int i = tid; i < 32 * 16; i += 256) sW2[i] = W2[i];
    if (tid < 32) sb1[tid] = b1[tid];
    if (tid < 16) { sb2[tid] = b2[tid]; sW3[tid] = W3[tid]; }
    if (tid == 0) sb3 = b3[0];
    __syncthreads();
    int g = tid;
    float inv = 1.f / fmaxf((float)g_gcount[g], 1.f);
    float x[64];
    #pragma unroll
    for (int k = 0; k < 64; k++) x[k] = g_hg[g * 64 + k] * inv;
    float y[32];
    #pragma unroll
    for (int j = 0; j < 32; j++) {
        float a = sb1[j];
        #pragma unroll
        for (int k = 0; k < 64; k++) a += x[k] * sW1[k * 32 + j];
        y[j] = fmaxf(a, 0.f);
    }
    float z[16];
    #pragma unroll
    for (int j = 0; j < 16; j++) {
        float a = sb2[j];
        #pragma unroll
        for (int k = 0; k < 32; k++) a += y[k] * sW2[k * 16 + j];
        z[j] = fmaxf(a, 0.f);
    }
    float o = sb3;
    #pragma unroll
    for (int k = 0; k < 16; k++) o += z[k] * sW3[k];
    out[g] = o;
}

// ---------------- launch ----------------
extern "C" void kernel_launch(void* const* d_in, const int* in_sizes, int n_in,
                              void* d_out, int out_size) {
    const int*   h         = (const int*)d_in[0];
    const int*   e         = (const int*)d_in[1];
    const int*   src       = (const int*)d_in[2];
    const int*   dst       = (const int*)d_in[3];
    const int*   graph_ids = (const int*)d_in[4];
    const float* node_emb  = (const float*)d_in[5];
    const float* edge_emb  = (const float*)d_in[6];
    const float* bn_h_g    = (const float*)d_in[7];
    const float* bn_h_b    = (const float*)d_in[8];
    const float* bn_e_g    = (const float*)d_in[9];
    const float* bn_e_b    = (const float*)d_in[10];
    const float* W1        = (const float*)d_in[11];
    const float* b1        = (const float*)d_in[12];
    const float* W2        = (const float*)d_in[13];
    const float* b2        = (const float*)d_in[14];
    const float* W3        = (const float*)d_in[15];
    const float* b3        = (const float*)d_in[16];
    float* out = (float*)d_out;

    const int NODE_WARP_BLOCKS = (N_NODES_C + 7) / 8;
    const int NL_BLOCKS = (N_NODES_C * 32 + 255) / 256;

    k_init<<<(N_NODES_C + 255) / 256, 256>>>();
    k_deg<<<(N_EDGES_C + 255) / 256, 256>>>(dst, graph_ids);
    k_nodeinit<<<NODE_WARP_BLOCKS, 256>>>(h, node_emb);
    k_scanA<<<N_TILES, SCAN_TILE>>>();
    k_scanB<<<1, 64>>>();
    k_scanC<<<N_TILES, SCAN_TILE>>>();
    k_permute<<<(N_EDGES_C + 255) / 256, 256>>>(e, src, dst, h);

    k_fused<0><<<NODE_WARP_BLOCKS, 256>>>(edge_emb, node_emb, bn_e_g, bn_e_b);
    k_Bh<<<NL_BLOCKS, 256>>>(0, bn_h_g, bn_h_b);
    k_fused<1><<<NODE_WARP_BLOCKS, 256>>>(edge_emb, node_emb, bn_e_g, bn_e_b);
    k_Bh<<<NL_BLOCKS, 256>>>(1, bn_h_g, bn_h_b);
    k_fused<2><<<NODE_WARP_BLOCKS, 256>>>(edge_emb, node_emb, bn_e_g, bn_e_b);
    k_Bh<<<NL_BLOCKS, 256>>>(2, bn_h_g, bn_h_b);
    k_fused<3><<<NODE_WARP_BLOCKS, 256>>>(edge_emb, node_emb, bn_e_g, bn_e_b);
    k_BhPool<<<NL_BLOCKS, 256>>>(graph_ids, bn_h_g, bn_h_b);

    k_mlp<<<1, 256>>>(W1, b1, W2, b2, W3, b3, out);
    (void)in_sizes; (void)n_in; (void)out_size;
}

// round 17
// speedup vs baseline: 1.1134x; 1.0177x over previous
#include <cuda_runtime.h>
#include <cuda_fp16.h>

#define N_NODES_C 50000
#define N_EDGES_C 800000
#define HID_C 64
#define N_GRAPHS_C 256
#define BN_EPS_C 1e-5f
#define GATE_EPS_C 1e-6f
#define SCAN_TILE 1024
#define N_TILES ((N_NODES_C + SCAN_TILE - 1) / SCAN_TILE)

typedef unsigned long long ull;

// ---------------- persistent device scratch ----------------
__device__ float4 g_hfi[(size_t)N_NODES_C * 32];
__device__ __half2 g_efh[(size_t)N_EDGES_C * 32];  // edge features fp16 (dst-sorted)
__device__ float g_hpre[N_NODES_C * HID_C];        // pre-BN h_new
__device__ float g_norm[N_NODES_C];
__device__ int   g_deg[N_NODES_C];
__device__ int   g_cursor[N_NODES_C];
__device__ int   g_rowptr[N_NODES_C + 1];
__device__ int   g_srcs[N_EDGES_C];                // packed: src(16) | etype(2)<<16 | hidx(7)<<18
__device__ int   g_bsum[N_TILES];
__device__ int   g_boff[N_TILES];
__device__ float g_stats4[4][256];                 // per-layer [se, se2, sh, sh2]
__device__ float g_hg[N_GRAPHS_C * HID_C];
__device__ int   g_gcount[N_GRAPHS_C];

// ---- streaming (evict-first) access helpers for the big ef array ----
__device__ __forceinline__ ull mk_policy() {
    ull p;
    asm volatile("createpolicy.fractional.L2::evict_first.b64 %0, 1.0;" : "=l"(p));
    return p;
}
__device__ __forceinline__ unsigned ld_stream_b32(const void* ptr, ull pol) {
    unsigned v;
    asm volatile("ld.global.L2::cache_hint.b32 %0, [%1], %2;"
                 : "=r"(v) : "l"(ptr), "l"(pol));
    return v;
}
__device__ __forceinline__ void st_stream_b32(void* ptr, unsigned v, ull pol) {
    asm volatile("st.global.L2::cache_hint.b32 [%0], %1, %2;"
                 :: "l"(ptr), "r"(v), "l"(pol));
}

// ---- packed f32x2 helpers (sm_100+ FFMA2 path, PTX-only) ----
__device__ __forceinline__ ull f2pk(float x, float y) {
    ull r; asm("mov.b64 %0, {%1, %2};" : "=l"(r) : "f"(x), "f"(y)); return r;
}
__device__ __forceinline__ void f2un(ull p, float& x, float& y) {
    asm("mov.b64 {%0, %1}, %2;" : "=f"(x), "=f"(y) : "l"(p));
}
__device__ __forceinline__ ull add2(ull a, ull b) {
    ull d; asm("add.rn.f32x2 %0, %1, %2;" : "=l"(d) : "l"(a), "l"(b)); return d;
}
__device__ __forceinline__ ull mul2(ull a, ull b) {
    ull d; asm("mul.rn.f32x2 %0, %1, %2;" : "=l"(d) : "l"(a), "l"(b)); return d;
}
__device__ __forceinline__ ull fma2(ull a, ull b, ull c) {
    ull d; asm("fma.rn.f32x2 %0, %1, %2, %3;" : "=l"(d) : "l"(a), "l"(b), "l"(c)); return d;
}

// sigmoid via single-MUFU hardware tanh: sigma(x) = 0.5*tanh(x/2) + 0.5
__device__ __forceinline__ float fast_sigmoid(float x) {
    float t;
    asm("tanh.approx.f32 %0, %1;" : "=f"(t) : "f"(x * 0.5f));
    return fmaf(t, 0.5f, 0.5f);
}

// BN scale/shift for one feature from raw sums
__device__ __forceinline__ void bn_coeff(float s, float s2, float invN,
                                         float gamma, float beta,
                                         float& scale, float& shift) {
    float mu = s * invN;
    float var = s2 * invN - mu * mu;
    scale = gamma * rsqrtf(var + BN_EPS_C);
    shift = beta - mu * scale;
}

// ---------------- prep kernels (R9/R12-proven structure) ----------------

__global__ void k_init() {
    int i = blockIdx.x * blockDim.x + threadIdx.x;
    if (i < N_NODES_C) { g_deg[i] = 0; g_cursor[i] = 0; }
    if (i < N_GRAPHS_C * HID_C) g_hg[i] = 0.f;
    if (i < N_GRAPHS_C) g_gcount[i] = 0;
    if (i < 4 * 256) ((float*)g_stats4)[i] = 0.f;
}

__global__ void k_deg(const int* __restrict__ dst, const int* __restrict__ graph_ids) {
    int i = blockIdx.x * blockDim.x + threadIdx.x;
    if (i < N_EDGES_C) atomicAdd(&g_deg[dst[i]], 1);
    if (i < N_NODES_C) atomicAdd(&g_gcount[graph_ids[i]], 1);
}

__global__ void k_nodeinit(const int* __restrict__ h, const float* __restrict__ node_emb) {
    int tid = threadIdx.x;
    int warp = tid >> 5, lane = tid & 31;
    int n = blockIdx.x * 8 + warp;
    if (n >= N_NODES_C) return;
    if (lane == 0) g_norm[n] = rsqrtf(fmaxf((float)g_deg[n], 1.f));
    int hi = h[n];
    float2 v = *(const float2*)(node_emb + hi * HID_C + 2 * lane);
    g_hfi[(size_t)n * 32 + lane] = make_float4(v.x, v.y, v.x, v.y);
}

__global__ void k_scanA() {
    __shared__ int s[32];
    int b = blockIdx.x, tid = threadIdx.x;
    int i = b * SCAN_TILE + tid;
    int v = (i < N_NODES_C) ? g_deg[i] : 0;
    #pragma unroll
    for (int off = 16; off > 0; off >>= 1) v += __shfl_down_sync(0xFFFFFFFFu, v, off);
    if ((tid & 31) == 0) s[tid >> 5] = v;
    __syncthreads();
    if (tid < 32) {
        int w = s[tid];
        #pragma unroll
        for (int off = 16; off > 0; off >>= 1) w += __shfl_down_sync(0xFFFFFFFFu, w, off);
        if (tid == 0) g_bsum[b] = w;
    }
}

__global__ void k_scanB() {
    int tid = threadIdx.x;
    int v = (tid < N_TILES) ? g_bsum[tid] : 0;
    int x = v;
    #pragma unroll
    for (int off = 1; off < 64; off <<= 1) {
        int t = __shfl_up_sync(0xFFFFFFFFu, x, off);
        if ((tid & 31) >= off) x += t;
    }
    __shared__ int s_half;
    if (tid == 31) s_half = x;
    __syncthreads();
    if (tid >= 32) x += s_half;
    if (tid < N_TILES) g_boff[tid] = x - v;
}

__global__ void k_scanC() {
    __shared__ int s_warp[32];
    int b = blockIdx.x, tid = threadIdx.x;
    int lane = tid & 31, warp = tid >> 5;
    int i = b * SCAN_TILE + tid;
    int v = (i < N_NODES_C) ? g_deg[i] : 0;
    int x = v;
    #pragma unroll
    for (int off = 1; off < 32; off <<= 1) {
        int t = __shfl_up_sync(0xFFFFFFFFu, x, off);
        if (lane >= off) x += t;
    }
    if (lane == 31) s_warp[warp] = x;
    __syncthreads();
    if (warp == 0) {
        int w = s_warp[lane];
        #pragma unroll
        for (int off = 1; off < 32; off <<= 1) {
            int t = __shfl_up_sync(0xFFFFFFFFu, w, off);
            if (lane >= off) w += t;
        }
        s_warp[lane] = w;
    }
    __syncthreads();
    int incl = x + (warp > 0 ? s_warp[warp - 1] : 0) + g_boff[b];
    if (i < N_NODES_C) g_rowptr[i + 1] = incl;
    if (b == 0 && tid == 0) g_rowptr[0] = 0;
}

// counting-sort permute; packs src | etype<<16 | h[src]<<18
__global__ void k_permute(const int* __restrict__ e, const int* __restrict__ src,
                          const int* __restrict__ dst, const int* __restrict__ h) {
    int i = blockIdx.x * blockDim.x + threadIdx.x;
    if (i >= N_EDGES_C) return;
    int d = dst[i];
    int s = src[i];
    int pos = g_rowptr[d] + atomicAdd(&g_cursor[d], 1);
    g_srcs[pos] = s | (e[i] << 16) | (h[s] << 18);
}

// ---------------- fused layer pass ----------------
// 1 warp/node, 4-wide batched gathers (MLP=4), 4 blocks/SM (32 resident warps),
// per-edge arithmetic in packed f32x2 (FFMA2) to halve FMA-pipe issue.
template<int L>
__global__ void __launch_bounds__(256, 4) k_fused(const float* __restrict__ edge_emb,
                                                  const float* __restrict__ node_emb,
                                                  const float* __restrict__ beg_,
                                                  const float* __restrict__ beb) {
    __shared__ float s_emb[4 * HID_C];
    __shared__ float s_acc[256];
    int tid = threadIdx.x;
    if (L <= 1) s_emb[tid] = edge_emb[tid];
    s_acc[tid] = 0.f;
    __syncthreads();
    int warp = tid >> 5, lane = tid & 31;
    int n = blockIdx.x * 8 + warp;
    if (n < N_NODES_C) {
        ull pol = mk_policy();
        float4 f4 = g_hfi[(size_t)n * 32 + lane];
        ull hdc2 = f2pk(f4.x, f4.y);
        ull hdp2 = f2pk(f4.z, f4.w);
        ull sce2 = 0, she2 = 0;
        if (L >= 1) {
            const float* st = g_stats4[L - 1];
            const float invE = 1.f / (float)N_EDGES_C;
            int f0 = 2 * lane, f1 = 2 * lane + 1;
            float sx, hx, sy, hy;
            bn_coeff(st[f0], st[64 + f0], invE,
                     __ldg(beg_ + (L - 1) * HID_C + f0), __ldg(beb + (L - 1) * HID_C + f0),
                     sx, hx);
            bn_coeff(st[f1], st[64 + f1], invE,
                     __ldg(beg_ + (L - 1) * HID_C + f1), __ldg(beb + (L - 1) * HID_C + f1),
                     sy, hy);
            sce2 = f2pk(sx, sy);
            she2 = f2pk(hx, hy);
        }
        float nn = g_norm[n];
        ull m2 = 0, d2 = 0, se2s = 0, se2q = 0;   // packed accumulators (0 == (0.f,0.f))
        int beg = g_rowptr[n], end = g_rowptr[n + 1];

        auto fetch_nf = [&](int sp, float2& nc, float2& np) {
            int s = sp & 0xFFFF;
            if (L == 0) {
                int hidx = (sp >> 18) & 0x7F;
                nc = __ldg((const float2*)(node_emb + hidx * HID_C + 2 * lane));
                np = make_float2(0.f, 0.f);
            } else if (L == 1) {
                nc = *(const float2*)&g_hfi[(size_t)s * 32 + lane];   // cur half (8B)
                int hidx = (sp >> 18) & 0x7F;
                np = __ldg((const float2*)(node_emb + hidx * HID_C + 2 * lane));
            } else {
                float4 v = g_hfi[(size_t)s * 32 + lane];
                nc = make_float2(v.x, v.y);
                np = make_float2(v.z, v.w);
            }
        };

        auto compute = [&](int k, float2 nc, float2 np, float ns, unsigned rawu) {
            ull nc2 = f2pk(nc.x, nc.y);
            ull raw2;
            if (L <= 1) {
                // rawu is an index into s_emb (etype*HID_C)
                raw2 = f2pk(s_emb[rawu + 2 * lane], s_emb[rawu + 2 * lane + 1]);
            } else {
                float2 r = __half22float2(*(__half2*)&rawu);
                raw2 = f2pk(r.x, r.y);
            }
            ull ef2;
            if (L == 0) {
                ef2 = raw2;
            } else {
                ull np2 = f2pk(np.x, np.y);
                ull ep2 = add2(add2(np2, hdp2), raw2);
                ull t2 = fma2(ep2, sce2, she2);
                float tx, ty; f2un(t2, tx, ty);
                tx = fmaxf(tx, 0.f); ty = fmaxf(ty, 0.f);
                ef2 = add2(raw2, f2pk(tx, ty));
                if (L < 3) {
                    float ex_, ey_; f2un(ef2, ex_, ey_);
                    __half2 hv = __floats2half2_rn(ex_, ey_);
                    st_stream_b32(&g_efh[(size_t)k * 32 + lane], *(unsigned*)&hv, pol);
                }
            }
            ull ex2 = add2(add2(nc2, hdc2), ef2);
            float ex, ey; f2un(ex2, ex, ey);
            float sgx = fast_sigmoid(ex);
            float sgy = fast_sigmoid(ey);
            ull sg2 = f2pk(sgx, sgy);
            ull ns2 = f2pk(ns, ns);
            m2 = fma2(mul2(sg2, nc2), ns2, m2);
            d2 = add2(d2, sg2);
            if (L < 3) {
                se2s = add2(se2s, ex2);
                se2q = fma2(ex2, ex2, se2q);
            }
        };

        int k = beg;
        for (; k + 3 < end; k += 4) {
            int sp[4];
            #pragma unroll
            for (int j = 0; j < 4; j++) sp[j] = g_srcs[k + j];
            float2 nc[4], np[4];
            #pragma unroll
            for (int j = 0; j < 4; j++) fetch_nf(sp[j], nc[j], np[j]);
            float ns[4];
            #pragma unroll
            for (int j = 0; j < 4; j++) ns[j] = g_norm[sp[j] & 0xFFFF];
            unsigned raw[4];
            #pragma unroll
            for (int j = 0; j < 4; j++) {
                if (L <= 1) raw[j] = ((unsigned)(sp[j] >> 16) & 3u) * HID_C;
                else raw[j] = ld_stream_b32(&g_efh[(size_t)(k + j) * 32 + lane], pol);
            }
            #pragma unroll
            for (int j = 0; j < 4; j++) compute(k + j, nc[j], np[j], ns[j], raw[j]);
        }
        for (; k < end; k++) {
            int sp = g_srcs[k];
            float2 nc, np;
            fetch_nf(sp, nc, np);
            float ns = g_norm[sp & 0xFFFF];
            unsigned raw;
            if (L <= 1) raw = ((unsigned)(sp >> 16) & 3u) * HID_C;
            else raw = ld_stream_b32(&g_efh[(size_t)k * 32 + lane], pol);
            compute(k, nc, np, ns, raw);
        }

        float mx, my, dx, dy;
        f2un(m2, mx, my);
        f2un(d2, dx, dy);
        float hdcx, hdcy; f2un(hdc2, hdcx, hdcy);
        float hpx = (hdcx * nn + mx / (dx + GATE_EPS_C)) * nn;
        float hpy = (hdcy * nn + my / (dy + GATE_EPS_C)) * nn;
        *(float2*)(&g_hpre[n * HID_C + 2 * lane]) = make_float2(hpx, hpy);
        if (L < 3) {
            float sex, sey, se2x, se2y;
            f2un(se2s, sex, sey);
            f2un(se2q, se2x, se2y);
            atomicAdd(&s_acc[2 * lane], sex);
            atomicAdd(&s_acc[2 * lane + 1], sey);
            atomicAdd(&s_acc[64 + 2 * lane], se2x);
            atomicAdd(&s_acc[64 + 2 * lane + 1], se2y);
        }
        atomicAdd(&s_acc[128 + 2 * lane], hpx);
        atomicAdd(&s_acc[128 + 2 * lane + 1], hpy);
        atomicAdd(&s_acc[192 + 2 * lane], hpx * hpx);
        atomicAdd(&s_acc[192 + 2 * lane + 1], hpy * hpy);
    }
    __syncthreads();
    atomicAdd(&g_stats4[L][tid], s_acc[tid]);
}

// node update: (cur, prev) -> (cur + relu(BN_l(hpre)), cur); BN coeffs from g_stats4[l]
__global__ void k_Bh(int l, const float* __restrict__ bhg, const float* __restrict__ bhb) {
    int i = blockIdx.x * blockDim.x + threadIdx.x;
    if (i >= N_NODES_C * 32) return;
    int lane = i & 31;
    const float* st = g_stats4[l];
    const float invN = 1.f / (float)N_NODES_C;
    int f0 = 2 * lane, f1 = 2 * lane + 1;
    float scx, shx, scy, shy;
    bn_coeff(st[128 + f0], st[192 + f0], invN,
             __ldg(bhg + l * HID_C + f0), __ldg(bhb + l * HID_C + f0), scx, shx);
    bn_coeff(st[128 + f1], st[192 + f1], invN,
             __ldg(bhg + l * HID_C + f1), __ldg(bhb + l * HID_C + f1), scy, shy);
    float4 f4 = g_hfi[i];
    float2 hp = *(const float2*)(&g_hpre[i * 2]);
    float vx = fmaxf(hp.x * scx + shx, 0.f);
    float vy = fmaxf(hp.y * scy + shy, 0.f);
    g_hfi[i] = make_float4(f4.x + vx, f4.y + vy, f4.x, f4.y);
}

// final node update (layer 3) fused with per-graph sum pooling
__global__ void k_BhPool(const int* __restrict__ graph_ids,
                         const float* __restrict__ bhg, const float* __restrict__ bhb) {
    int i = blockIdx.x * blockDim.x + threadIdx.x;
    if (i >= N_NODES_C * 32) return;
    int lane = i & 31;
    int n = i >> 5;
    const float* st = g_stats4[3];
    const float invN = 1.f / (float)N_NODES_C;
    int f0 = 2 * lane, f1 = 2 * lane + 1;
    float scx, shx, scy, shy;
    bn_coeff(st[128 + f0], st[192 + f0], invN,
             __ldg(bhg + 3 * HID_C + f0), __ldg(bhb + 3 * HID_C + f0), scx, shx);
    bn_coeff(st[128 + f1], st[192 + f1], invN,
             __ldg(bhg + 3 * HID_C + f1), __ldg(bhb + 3 * HID_C + f1), scy, shy);
    float4 f4 = g_hfi[i];
    float2 hp = *(const float2*)(&g_hpre[i * 2]);
    float vx = f4.x + fmaxf(hp.x * scx + shx, 0.f);
    float vy = f4.y + fmaxf(hp.y * scy + shy, 0.f);
    int g = graph_ids[n];
    atomicAdd(&g_hg[(g << 6) + f0], vx);
    atomicAdd(&g_hg[(g << 6) + f1], vy);
}

// final 3-layer MLP, one thread per graph
__global__ void k_mlp(const float* __restrict__ W1, const float* __restrict__ b1,
                      const float* __restrict__ W2, const float* __restrict__ b2,
                      const float* __restrict__ W3, const float* __restrict__ b3,
                      float* __restrict__ out) {
    __shared__ float sW1[64 * 32], sW2[32 * 16], sb1[32], sb2[16], sW3[16], sb3;
    int tid = threadIdx.x;
    for (int i = tid; i < 64 * 32; i += 256) sW1[i] = W1[i];
    for (int i = tid; i < 32 * 16; i += 256) sW2[i] = W2[i];
    if (tid < 32) sb1[tid] = b1[tid];
    if (tid < 16) { sb2[tid] = b2[tid]; sW3[tid] = W3[tid]; }
    if (tid == 0) sb3 = b3[0];
    __syncthreads();
    int g = tid;
    float inv = 1.f / fmaxf((float)g_gcount[g], 1.f);
    float x[64];
    #pragma unroll
    for (int k = 0; k < 64; k++) x[k] = g_hg[g * 64 + k] * inv;
    float y[32];
    #pragma unroll
    for (int j = 0; j < 32; j++) {
        float a = sb1[j];
        #pragma unroll
        for (int k = 0; k < 64; k++) a += x[k] * sW1[k * 32 + j];
        y[j] = fmaxf(a, 0.f);
    }
    float z[16];
    #pragma unroll
    for (int j = 0; j < 16; j++) {
        float a = sb2[j];
        #pragma unroll
        for (int k = 0; k < 32; k++) a += y[k] * sW2[k * 16 + j];
        z[j] = fmaxf(a, 0.f);
    }
    float o = sb3;
    #pragma unroll
    for (int k = 0; k < 16; k++) o += z[k] * sW3[k];
    out[g] = o;
}

// ---------------- launch ----------------
extern "C" void kernel_launch(void* const* d_in, const int* in_sizes, int n_in,
                              void* d_out, int out_size) {
    const int*   h         = (const int*)d_in[0];
    const int*   e         = (const int*)d_in[1];
    const int*   src       = (const int*)d_in[2];
    const int*   dst       = (const int*)d_in[3];
    const int*   graph_ids = (const int*)d_in[4];
    const float* node_emb  = (const float*)d_in[5];
    const float* edge_emb  = (const float*)d_in[6];
    const float* bn_h_g    = (const float*)d_in[7];
    const float* bn_h_b    = (const float*)d_in[8];
    const float* bn_e_g    = (const float*)d_in[9];
    const float* bn_e_b    = (const float*)d_in[10];
    const float* W1        = (const float*)d_in[11];
    const float* b1        = (const float*)d_in[12];
    const float* W2        = (const float*)d_in[13];
    const float* b2        = (const float*)d_in[14];
    const float* W3        = (const float*)d_in[15];
    const float* b3        = (const float*)d_in[16];
    float* out = (float*)d_out;

    const int NODE_WARP_BLOCKS = (N_NODES_C + 7) / 8;
    const int NL_BLOCKS = (N_NODES_C * 32 + 255) / 256;

    k_init<<<(N_NODES_C + 255) / 256, 256>>>();
    k_deg<<<(N_EDGES_C + 255) / 256, 256>>>(dst, graph_ids);
    k_nodeinit<<<NODE_WARP_BLOCKS, 256>>>(h, node_emb);
    k_scanA<<<N_TILES, SCAN_TILE>>>();
    k_scanB<<<1, 64>>>();
    k_scanC<<<N_TILES, SCAN_TILE>>>();
    k_permute<<<(N_EDGES_C + 255) / 256, 256>>>(e, src, dst, h);

    k_fused<0><<<NODE_WARP_BLOCKS, 256>>>(edge_emb, node_emb, bn_e_g, bn_e_b);
    k_Bh<<<NL_BLOCKS, 256>>>(0, bn_h_g, bn_h_b);
    k_fused<1><<<NODE_WARP_BLOCKS, 256>>>(edge_emb, node_emb, bn_e_g, bn_e_b);
    k_Bh<<<NL_BLOCKS, 256>>>(1, bn_h_g, bn_h_b);
    k_fused<2><<<NODE_WARP_BLOCKS, 256>>>(edge_emb, node_emb, bn_e_g, bn_e_b);
    k_Bh<<<NL_BLOCKS, 256>>>(2, bn_h_g, bn_h_b);
    k_fused<3><<<NODE_WARP_BLOCKS, 256>>>(edge_emb, node_emb, bn_e_g, bn_e_b);
    k_BhPool<<<NL_BLOCKS, 256>>>(graph_ids, bn_h_g, bn_h_b);

    k_mlp<<<1, 256>>>(W1, b1, W2, b2, W3, b3, out);
    (void)in_sizes; (void)n_in; (void)out_size;
}